// round 9
// baseline (speedup 1.0000x reference)
#include <cuda_runtime.h>
#include <math.h>

#define THREADS 256
#define STAGES  8                       // power of 2: ring index is an AND
#define CPT     THREADS                 // 16B chunks per tile (1 per thread)
#define SPLIT   4                       // segments per row

__device__ int          g_rank[4096 * SPLIT];
__device__ int          g_pos [4096 * SPLIT];
__device__ float        g_xs  [4096 * SPLIT];
__device__ unsigned int g_done = 0;     // reset by the finisher each launch

__device__ __forceinline__ void cp_async16(void* smem_dst, const void* gsrc) {
    unsigned saddr = (unsigned)__cvta_generic_to_shared(smem_dst);
    asm volatile("cp.async.cg.shared.global [%0], [%1], 16;\n"
                 :: "r"(saddr), "l"(gsrc));
}
__device__ __forceinline__ void cp_async_commit() {
    asm volatile("cp.async.commit_group;\n" ::: "memory");
}
template<int N>
__device__ __forceinline__ void cp_async_wait() {
    asm volatile("cp.async.wait_group %0;\n" :: "n"(N) : "memory");
}

__global__ __launch_bounds__(THREADS)
void wrpl_seg_kernel(const float* __restrict__ scores,
                     const int* __restrict__ targets,
                     float* __restrict__ out,
                     int B, int C)
{
    // Thread-private 16B slots -> no cross-thread smem sharing -> no barriers
    // in the streaming loop; cp.async.wait_group orders own write/read.
    __shared__ float4 buf[STAGES][CPT];          // 32 KB

    const int unit = blockIdx.x;                 // B*SPLIT units
    const int row  = unit >> 2;                  // SPLIT == 4
    const int seg  = unit & (SPLIT - 1);
    const float* s = scores + (size_t)row * (size_t)C;
    const int t  = targets[row];
    const int td = threadIdx.x;

    const float gt  = __ldg(s + t);
    const float thr = gt - 1.0f;                 // hinge: l > 0 <=> x > gt-1
    const float gtb = nextafterf(gt, -__int_as_float(0x7f800000)); // x>gtb <=> x>=gt

    const int nChunks = C >> 2;                  // C % 4 == 0
    const int begin   = (seg * nChunks) / SPLIT;
    const int end     = ((seg + 1) * nChunks) / SPLIT;
    const int nTiles  = (end - begin + CPT - 1) / CPT;
    const int tb      = t >> 2;                  // chunk containing j == t

    const float4* s4 = reinterpret_cast<const float4*>(s);

    int   cnt_rank = 0;
    int   cnt_pos  = 0;
    float xsum     = 0.0f;

    // ---- prologue: fill STAGES-2 stages ----
    #pragma unroll
    for (int pt = 0; pt < STAGES - 2; ++pt) {
        int c4 = begin + pt * CPT + td;
        if (pt < nTiles && c4 < end)
            cp_async16(&buf[pt][td], s4 + c4);
        cp_async_commit();
    }

    // ---- streaming loop: branch-free compare, barrier-free ----
    for (int tile = 0; tile < nTiles; ++tile) {
        const int it = tile + STAGES - 2;
        if (it < nTiles) {
            int c4i = begin + it * CPT + td;
            if (c4i < end)
                cp_async16(&buf[it & (STAGES - 1)][td], s4 + c4i);
        }
        cp_async_commit();
        cp_async_wait<STAGES - 2>();             // own tile `tile` complete

        const int c4 = begin + tile * CPT + td;
        if (c4 < end) {
            // chunks <= tb counted with GE semantics (th=gtb), > tb with GT
            const float th = (c4 <= tb) ? gtb : gt;
            float4 v = buf[tile & (STAGES - 1)][td];
            { float x = v.x; cnt_rank += (x > th); bool p = (x > thr); cnt_pos += p; if (p) xsum += x; }
            { float x = v.y; cnt_rank += (x > th); bool p = (x > thr); cnt_pos += p; if (p) xsum += x; }
            { float x = v.z; cnt_rank += (x > th); bool p = (x > thr); cnt_pos += p; if (p) xsum += x; }
            { float x = v.w; cnt_rank += (x > th); bool p = (x > thr); cnt_pos += p; if (p) xsum += x; }
        }
    }

    // ---- exact boundary correction (only the segment containing tb) ----
    //   idx == t          : rank -= 1, pos -= 1, xsum -= gt
    //   idx  > t, x == gt : rank -= 1  (counted under GE, should be GT)
    if (td == 0 && tb >= begin && tb < end) {
        const int base = tb << 2;
        #pragma unroll
        for (int e = 0; e < 4; ++e) {
            const int idx = base + e;
            const float x = __ldg(s + idx);
            if (idx == t) {
                cnt_rank -= 1;
                cnt_pos  -= 1;
                xsum     -= gt;
            } else if (idx > t && x == gt) {
                cnt_rank -= 1;
            }
        }
    }

    // ---- block reduction ----
    const unsigned FULL = 0xFFFFFFFFu;
    #pragma unroll
    for (int off = 16; off > 0; off >>= 1) {
        cnt_rank += __shfl_down_sync(FULL, cnt_rank, off);
        cnt_pos  += __shfl_down_sync(FULL, cnt_pos,  off);
        xsum     += __shfl_down_sync(FULL, xsum,     off);
    }

    __shared__ int   sh_rk [THREADS / 32];
    __shared__ int   sh_pos[THREADS / 32];
    __shared__ float sh_xs [THREADS / 32];
    __shared__ bool  sh_last;

    const int lane = td & 31;
    const int wid  = td >> 5;
    if (lane == 0) {
        sh_rk[wid]  = cnt_rank;
        sh_pos[wid] = cnt_pos;
        sh_xs[wid]  = xsum;
    }
    __syncthreads();

    if (td == 0) {
        int   rk = 0, p = 0;
        float xs = 0.0f;
        #pragma unroll
        for (int i = 0; i < THREADS / 32; i++) {
            rk += sh_rk[i]; p += sh_pos[i]; xs += sh_xs[i];
        }
        g_rank[unit] = rk;
        g_pos [unit] = p;
        g_xs  [unit] = xs;

        __threadfence();                         // publish partials
        unsigned ticket = atomicAdd(&g_done, 1u);
        sh_last = (ticket == (unsigned)(gridDim.x - 1));
    }
    __syncthreads();

    // ---- finisher: last CTA fuses segments, computes per-row loss, mean ----
    if (sh_last) {
        float acc = 0.0f;
        for (int r = td; r < B; r += THREADS) {
            int   rk = 0, p = 0;
            float xs = 0.0f;
            #pragma unroll
            for (int sg = 0; sg < SPLIT; ++sg) {
                const int u = r * SPLIT + sg;
                rk += g_rank[u];
                p  += g_pos [u];
                xs += g_xs  [u];
            }
            const int   tt   = targets[r];
            const float gtr  = __ldg(scores + (size_t)r * (size_t)C + tt);
            const float thrr = gtr - 1.0f;
            const int   rank = rk + 1;
            const float hinge = xs - (float)p * thrr;

            double H;
            if (rank <= 64) {
                H = 0.0;
                for (int i = 1; i <= rank; i++) H += 1.0 / (double)i;
            } else {
                double n  = (double)rank;
                double n2 = n * n;
                H = log(n) + 0.57721566490153286
                  + 1.0 / (2.0 * n) - 1.0 / (12.0 * n2) + 1.0 / (120.0 * n2 * n2);
            }
            acc += (float)H / ((float)p + 1e-7f) * hinge;
        }

        #pragma unroll
        for (int off = 16; off > 0; off >>= 1)
            acc += __shfl_down_sync(FULL, acc, off);

        __shared__ float sh_fin[THREADS / 32];
        if (lane == 0) sh_fin[wid] = acc;
        __syncthreads();
        if (td == 0) {
            float total = 0.0f;
            #pragma unroll
            for (int i = 0; i < THREADS / 32; i++) total += sh_fin[i];
            out[0] = total / (float)B;
            g_done = 0;                          // reset for next launch
        }
    }
}

extern "C" void kernel_launch(void* const* d_in, const int* in_sizes, int n_in,
                              void* d_out, int out_size)
{
    const float* scores  = (const float*)d_in[0];
    const int*   targets = (const int*)d_in[1];
    float*       out     = (float*)d_out;

    const int B = in_sizes[1];
    const int C = in_sizes[0] / B;

    wrpl_seg_kernel<<<B * SPLIT, THREADS>>>(scores, targets, out, B, C);
}

// round 10
// speedup vs baseline: 1.6985x; 1.6985x over previous
#include <cuda_runtime.h>
#include <math.h>

#define THREADS 256
#define STAGES  8                       // power of 2: ring index is an AND
#define CPT     THREADS                 // 16B chunks per tile (1 per thread)

__global__ void wrpl_zero_out(float* out) {
    if (threadIdx.x == 0 && blockIdx.x == 0) out[0] = 0.0f;
}

__device__ __forceinline__ void cp_async16(void* smem_dst, const void* gsrc) {
    unsigned saddr = (unsigned)__cvta_generic_to_shared(smem_dst);
    asm volatile("cp.async.cg.shared.global [%0], [%1], 16;\n"
                 :: "r"(saddr), "l"(gsrc));
}
__device__ __forceinline__ void cp_async_commit() {
    asm volatile("cp.async.commit_group;\n" ::: "memory");
}
template<int N>
__device__ __forceinline__ void cp_async_wait() {
    asm volatile("cp.async.wait_group %0;\n" :: "n"(N) : "memory");
}

__global__ __launch_bounds__(THREADS)
void wrpl_row_kernel(const float* __restrict__ scores,
                     const int* __restrict__ targets,
                     float* __restrict__ out,
                     int B, int C)
{
    // Thread-private 16B slots -> no cross-thread smem sharing -> no barriers
    // in the streaming loop; cp.async.wait_group orders own write/read.
    __shared__ float4 buf[STAGES][CPT];          // 32 KB

    const int row = blockIdx.x;
    const float* s = scores + (size_t)row * (size_t)C;
    const int t  = targets[row];
    const int td = threadIdx.x;

    const float gt  = __ldg(s + t);
    const float thr = gt - 1.0f;                 // hinge: l > 0 <=> x > gt-1
    const float gtb = nextafterf(gt, -__int_as_float(0x7f800000)); // x>gtb <=> x>=gt

    const int nChunks = C >> 2;                  // C % 4 == 0 (C = 32000)
    const int nFull   = nChunks / CPT;           // full tiles (no bound checks)
    const int nTiles  = (nChunks + CPT - 1) / CPT;
    const int tb      = t >> 2;                  // chunk index containing j == t

    const float4* s4 = reinterpret_cast<const float4*>(s);

    int   cnt_rank = 0;
    int   cnt_pos  = 0;
    float xsum     = 0.0f;

    // ---- prologue: fill STAGES-2 stages (all full tiles: 6*256 < 8000) ----
    #pragma unroll
    for (int pt = 0; pt < STAGES - 2; ++pt) {
        int c4 = pt * CPT + td;
        if (c4 < nChunks)
            cp_async16(&buf[pt][td], s4 + c4);
        cp_async_commit();
    }

#define PROC4(vv, c4u)                                                         \
    {                                                                          \
        const float th = ((c4u) <= tb) ? gtb : gt;                             \
        { float x = (vv).x; cnt_rank += (x > th); bool p = (x > thr); cnt_pos += p; if (p) xsum += x; } \
        { float x = (vv).y; cnt_rank += (x > th); bool p = (x > thr); cnt_pos += p; if (p) xsum += x; } \
        { float x = (vv).z; cnt_rank += (x > th); bool p = (x > thr); cnt_pos += p; if (p) xsum += x; } \
        { float x = (vv).w; cnt_rank += (x > th); bool p = (x > thr); cnt_pos += p; if (p) xsum += x; } \
    }

    // ---- streaming loop over full tiles: no bound checks in the hot path ----
    for (int tile = 0; tile < nFull; ++tile) {
        const int it = tile + STAGES - 2;
        if (it < nTiles) {
            int c4i = it * CPT + td;
            if (c4i < nChunks)
                cp_async16(&buf[it & (STAGES - 1)][td], s4 + c4i);
        }
        cp_async_commit();
        cp_async_wait<STAGES - 2>();             // own tile `tile` complete

        const int c4 = tile * CPT + td;
        float4 v = buf[tile & (STAGES - 1)][td];
        PROC4(v, c4)
    }

    // ---- tail tile (partial), if any ----
    if (nTiles > nFull) {
        cp_async_commit();
        cp_async_wait<0>();
        const int c4 = nFull * CPT + td;
        if (c4 < nChunks) {
            float4 v = buf[nFull & (STAGES - 1)][td];
            PROC4(v, c4)
        }
    }
#undef PROC4

    // ---- exact correction for the boundary chunk (thread 0) ----
    //   idx == t          : rank -= 1, pos -= 1, xsum -= gt
    //   idx  > t, x == gt : rank -= 1  (counted under GE, should be GT)
    if (td == 0) {
        const int base = tb << 2;
        #pragma unroll
        for (int e = 0; e < 4; ++e) {
            const int idx = base + e;
            const float x = __ldg(s + idx);
            if (idx == t) {
                cnt_rank -= 1;
                cnt_pos  -= 1;
                xsum     -= gt;
            } else if (idx > t && x == gt) {
                cnt_rank -= 1;
            }
        }
    }

    // ---- block reduction ----
    const unsigned FULL = 0xFFFFFFFFu;
    #pragma unroll
    for (int off = 16; off > 0; off >>= 1) {
        cnt_rank += __shfl_down_sync(FULL, cnt_rank, off);
        cnt_pos  += __shfl_down_sync(FULL, cnt_pos,  off);
        xsum     += __shfl_down_sync(FULL, xsum,     off);
    }

    __shared__ int   sh_rk [THREADS / 32];
    __shared__ int   sh_pos[THREADS / 32];
    __shared__ float sh_xs [THREADS / 32];

    const int lane = td & 31;
    const int wid  = td >> 5;
    if (lane == 0) {
        sh_rk[wid]  = cnt_rank;
        sh_pos[wid] = cnt_pos;
        sh_xs[wid]  = xsum;
    }
    __syncthreads();

    if (td == 0) {
        int   rk = 0, p = 0;
        float xs = 0.0f;
        #pragma unroll
        for (int i = 0; i < THREADS / 32; i++) {
            rk += sh_rk[i]; p += sh_pos[i]; xs += sh_xs[i];
        }

        const int rank = rk + 1;
        const float hinge = xs - (float)p * thr;

        // harmonic number H(rank)
        double H;
        if (rank <= 64) {
            H = 0.0;
            for (int i = 1; i <= rank; i++) H += 1.0 / (double)i;
        } else {
            double n  = (double)rank;
            double n2 = n * n;
            H = log(n) + 0.57721566490153286
              + 1.0 / (2.0 * n) - 1.0 / (12.0 * n2) + 1.0 / (120.0 * n2 * n2);
        }

        float npos = (float)p + 1e-7f;
        float loss = (float)H / npos * hinge;
        atomicAdd(out, loss / (float)B);
    }
}

extern "C" void kernel_launch(void* const* d_in, const int* in_sizes, int n_in,
                              void* d_out, int out_size)
{
    const float* scores  = (const float*)d_in[0];
    const int*   targets = (const int*)d_in[1];
    float*       out     = (float*)d_out;

    const int B = in_sizes[1];
    const int C = in_sizes[0] / B;

    wrpl_zero_out<<<1, 32>>>(out);
    wrpl_row_kernel<<<B, THREADS>>>(scores, targets, out, B, C);
}

// round 11
// speedup vs baseline: 1.7228x; 1.0143x over previous
#include <cuda_runtime.h>
#include <math.h>

#define THREADS 256
#define STAGES  8                       // ring depth; STAGES-2 tiles in flight
#define CPT     THREADS                 // chunks (16B) per tile = 1 per thread

__device__ __forceinline__ void cp_async16(void* smem_dst, const void* gsrc) {
    unsigned saddr = (unsigned)__cvta_generic_to_shared(smem_dst);
    asm volatile("cp.async.cg.shared.global [%0], [%1], 16;\n"
                 :: "r"(saddr), "l"(gsrc));
}
__device__ __forceinline__ void cp_async_commit() {
    asm volatile("cp.async.commit_group;\n" ::: "memory");
}
template<int N>
__device__ __forceinline__ void cp_async_wait() {
    asm volatile("cp.async.wait_group %0;\n" :: "n"(N) : "memory");
}

__global__ __launch_bounds__(THREADS)
void wrpl_row_kernel(const float* __restrict__ scores,
                     const int* __restrict__ targets,
                     float* __restrict__ out,
                     int B, int C)
{
    // Each thread owns one 16B slot per stage -> no cross-thread smem sharing,
    // no __syncthreads in the streaming loop. wait_group orders own write/read.
    __shared__ float4 buf[STAGES][CPT];

    const int row = blockIdx.x;
    const float* s = scores + (size_t)row * (size_t)C;
    const int t = targets[row];

    const float gt  = __ldg(s + t);
    const float thr = gt - 1.0f;        // l > 0  <=>  s > gt - 1

    const int nChunks = C >> 2;         // float4 chunks per row (C % 4 == 0)
    const int nTiles  = (nChunks + CPT - 1) / CPT;
    const int tb      = t >> 2;         // chunk containing the target

    const float4* s4 = reinterpret_cast<const float4*>(s);
    const int td = threadIdx.x;

    int   cnt_rank = 0;   // #{j<t: s_j >= gt} + #{j>t: s_j > gt} = rank-1
    int   cnt_pos  = 0;   // #{j != t : s_j > thr}
    float xsum     = 0.0f;

    // ---- prologue: fill STAGES-2 stages ----
    #pragma unroll
    for (int pt = 0; pt < STAGES - 2; ++pt) {
        int c4 = pt * CPT + td;
        if (pt < nTiles && c4 < nChunks)
            cp_async16(&buf[pt][td], s4 + c4);
        cp_async_commit();
    }

#define PROC_GE(xv) { float x = (xv); cnt_rank += (x >= gt); bool p = (x > thr); cnt_pos += p; if (p) xsum += x; }
#define PROC_GT(xv) { float x = (xv); cnt_rank += (x >  gt); bool p = (x > thr); cnt_pos += p; if (p) xsum += x; }

    // ---- streaming loop: 1 issue + 1 wait per tile, no barriers ----
    for (int tile = 0; tile < nTiles; ++tile) {
        const int it = tile + STAGES - 2;
        if (it < nTiles) {
            int c4i = it * CPT + td;
            if (c4i < nChunks)
                cp_async16(&buf[it % STAGES][td], s4 + c4i);
        }
        cp_async_commit();
        cp_async_wait<STAGES - 2>();     // own tile `tile` is complete

        const int c4 = tile * CPT + td;
        if (c4 < nChunks) {
            float4 v = buf[tile % STAGES][td];
            if (c4 < tb) {               // all idx < t
                PROC_GE(v.x) PROC_GE(v.y) PROC_GE(v.z) PROC_GE(v.w)
            } else if (c4 > tb) {        // all idx > t
                PROC_GT(v.x) PROC_GT(v.y) PROC_GT(v.z) PROC_GT(v.w)
            } else {                     // boundary chunk: contains j == t
                const float xv[4] = {v.x, v.y, v.z, v.w};
                const int base = c4 << 2;
                #pragma unroll
                for (int e = 0; e < 4; ++e) {
                    int idx = base + e;
                    if (idx == t) continue;
                    float x = xv[e];
                    cnt_rank += (idx < t) ? (x >= gt) : (x > gt);
                    bool p = (x > thr);
                    cnt_pos += p;
                    if (p) xsum += x;
                }
            }
        }
    }
#undef PROC_GE
#undef PROC_GT

    // ---- block reduction ----
    const unsigned FULL = 0xFFFFFFFFu;
    #pragma unroll
    for (int off = 16; off > 0; off >>= 1) {
        cnt_rank += __shfl_down_sync(FULL, cnt_rank, off);
        cnt_pos  += __shfl_down_sync(FULL, cnt_pos,  off);
        xsum     += __shfl_down_sync(FULL, xsum,     off);
    }

    __shared__ int   sh_rk [THREADS / 32];
    __shared__ int   sh_pos[THREADS / 32];
    __shared__ float sh_xs [THREADS / 32];

    const int lane = td & 31;
    const int wid  = td >> 5;
    if (lane == 0) {
        sh_rk[wid]  = cnt_rank;
        sh_pos[wid] = cnt_pos;
        sh_xs[wid]  = xsum;
    }
    __syncthreads();

    if (td == 0) {
        int   rk = 0, p = 0;
        float xs = 0.0f;
        #pragma unroll
        for (int i = 0; i < THREADS / 32; i++) {
            rk += sh_rk[i]; p += sh_pos[i]; xs += sh_xs[i];
        }

        const int rank = rk + 1;
        const float hinge = xs - (float)p * thr;

        // harmonic number H(rank)
        double H;
        if (rank <= 64) {
            H = 0.0;
            for (int i = 1; i <= rank; i++) H += 1.0 / (double)i;
        } else {
            double n  = (double)rank;
            double n2 = n * n;
            H = log(n) + 0.57721566490153286
              + 1.0 / (2.0 * n) - 1.0 / (12.0 * n2) + 1.0 / (120.0 * n2 * n2);
        }

        float npos = (float)p + 1e-7f;
        float loss = (float)H / npos * hinge;
        atomicAdd(out, loss / (float)B);
    }
}

extern "C" void kernel_launch(void* const* d_in, const int* in_sizes, int n_in,
                              void* d_out, int out_size)
{
    const float* scores  = (const float*)d_in[0];
    const int*   targets = (const int*)d_in[1];
    float*       out     = (float*)d_out;

    const int B = in_sizes[1];
    const int C = in_sizes[0] / B;

    // graph memset node: cheaper than a zeroing kernel launch
    cudaMemsetAsync(out, 0, sizeof(float));
    wrpl_row_kernel<<<B, THREADS>>>(scores, targets, out, B, C);
}